// round 12
// baseline (speedup 1.0000x reference)
#include <cuda_runtime.h>
#include <math.h>

#define NB 16
#define NT 32768
#define NK 128
#define NS 256     // samples per segment (T/K)
#define NC 64      // in/out channels
#define NZ 64
#define NH 32

// Scratch (allocation-free: __device__ globals)
__device__ float g_wm2eff[4096 * 32];                 // KSZ-folded hypernet matrix
__device__ float g_wb2eff[4096];
__device__ float g_weff[(size_t)NB * NK * 4096];      // per-(b,k) 64x64 weights, [bk][i*64+o]
__device__ float g_bias[NB * NK * NC];                // per-(b,k) bias

// ---------------------------------------------------------------------------
// Kernel 1: fold the KSZ tap sum into wm2/wb2 (row r = cin*64+o; taps at
// r, 4096+r, 8192+r per the reshape (B,KSZ,Cin,OUT,K)).
// ---------------------------------------------------------------------------
__global__ void fold_kernel(const float* __restrict__ wm2,
                            const float* __restrict__ wb2)
{
    int idx = blockIdx.x * 256 + threadIdx.x;
    if (idx < 4096 * 32) {
        int r = idx >> 5, h = idx & 31;
        g_wm2eff[idx] = wm2[r * 32 + h] + wm2[(4096 + r) * 32 + h]
                      + wm2[(8192 + r) * 32 + h];
    }
    if (idx < 4096) {
        g_wb2eff[idx] = wb2[idx] + wb2[4096 + idx] + wb2[8192 + idx];
    }
}

// ---------------------------------------------------------------------------
// Kernel 2: hypernet. One block per (b, group of 16 k). Computes
//   h  = relu(wm1 @ z + wb1),  hb = relu(bm1 @ z + bb1)
//   w_eff[bk][r] = wm2eff[r] . h   (+ wb2eff),  bias[bk][o] = bm2[o] . hb + bb2
// Batching 16 k per block reuses the 512KB wm2eff through L2/registers.
// ---------------------------------------------------------------------------
__global__ void __launch_bounds__(256) hyper_kernel(
    const float* __restrict__ z,
    const float* __restrict__ wm1, const float* __restrict__ wb1,
    const float* __restrict__ bm1, const float* __restrict__ bb1,
    const float* __restrict__ bm2, const float* __restrict__ bb2)
{
    __shared__ float zsh[16 * 64];   // [kk][zc]
    __shared__ float hsh[16 * 32];   // [kk][h]
    __shared__ float hbsh[16 * 32];

    int tid = threadIdx.x;
    int b   = blockIdx.y;
    int k0  = blockIdx.x * 16;

    for (int idx = tid; idx < 16 * 64; idx += 256) {
        int zc = idx >> 4, kk = idx & 15;
        zsh[kk * 64 + zc] = z[((size_t)b * NZ + zc) * NK + k0 + kk];
    }
    __syncthreads();

    // 16 kk * (32 h + 32 hb) = 1024 hidden activations
    for (int oi = tid; oi < 1024; oi += 256) {
        int kk = oi >> 6;
        int j  = oi & 63;
        const float* m;
        float bv;
        if (j < 32) { m = wm1 + j * 64;        bv = wb1[j]; }
        else        { m = bm1 + (j - 32) * 64; bv = bb1[j - 32]; }
        float a = bv;
        #pragma unroll
        for (int zc = 0; zc < 64; zc++) a = fmaf(m[zc], zsh[kk * 64 + zc], a);
        a = fmaxf(a, 0.0f);
        if (j < 32) hsh[kk * 32 + j] = a;
        else        hbsh[kk * 32 + (j - 32)] = a;
    }
    __syncthreads();

    // 4096 weight rows; each thread keeps one wm2eff row in registers and
    // sweeps 16 k's with it.
    for (int r = tid; r < 4096; r += 256) {
        float wrow[32];
        const float4* wp = (const float4*)(g_wm2eff + (size_t)r * 32);
        #pragma unroll
        for (int q = 0; q < 8; q++) {
            float4 v = wp[q];
            wrow[q * 4 + 0] = v.x; wrow[q * 4 + 1] = v.y;
            wrow[q * 4 + 2] = v.z; wrow[q * 4 + 3] = v.w;
        }
        float wb = g_wb2eff[r];
        for (int kk = 0; kk < 16; kk++) {
            float a = wb;
            #pragma unroll
            for (int h = 0; h < 32; h++) a = fmaf(wrow[h], hsh[kk * 32 + h], a);
            g_weff[((size_t)(b * NK + k0 + kk)) * 4096 + r] = a;
        }
    }

    // per-(b,k) bias (64 outputs x 16 kk)
    for (int oi = tid; oi < 1024; oi += 256) {
        int kk = oi >> 6;
        int o  = oi & 63;
        float a = bb2[o];
        #pragma unroll
        for (int h = 0; h < 32; h++) a = fmaf(bm2[o * 32 + h], hbsh[kk * 32 + h], a);
        g_bias[((size_t)(b * NK + k0 + kk)) * NC + o] = a;
    }
}

// ---------------------------------------------------------------------------
// Kernel 3: fused main pass. One CTA per (b,k) segment.
//  Phase 1: y[s,o] = sum_i x[i,s] * w_eff[i,o] + bias[o];  ys = sin(y) -> smem
//  Phase 2: res[s,o] = rw . ys + rb;  skip[s,o] = sw . ys + sb
//  Epilogue: out_res = 0.5*(res + x),  out_skip = skip
// 256 threads, 8(s) x 8(o) register tile each (32 s-threads x 8 o-warps).
// ---------------------------------------------------------------------------
__global__ void __launch_bounds__(256, 1) main_kernel(
    const float* __restrict__ x,
    const float* __restrict__ rw, const float* __restrict__ rb,
    const float* __restrict__ sw, const float* __restrict__ sb,
    float* __restrict__ out_res, float* __restrict__ out_skip)
{
    extern __shared__ float sm[];
    float* xs   = sm;                 // [64][256] x segment
    float* ys   = xs + 64 * 256;      // [64][256] sin(y)
    float* wsh  = ys + 64 * 256;      // [64][64] w_eff (i, o)
    float* rwT  = wsh + 4096;         // [c][o]
    float* swT  = rwT + 4096;         // [c][o]
    float* bsh  = swT + 4096;         // [64]
    float* rbsh = bsh + 64;
    float* sbsh = rbsh + 64;

    int tid = threadIdx.x;
    int bk  = blockIdx.x;
    int b   = bk >> 7, k = bk & 127;

    // stage x segment: 64 rows x 256 floats (each row contiguous in global)
    const float* xg = x + ((size_t)b * NC) * NT + (size_t)k * NS;
    for (int idx = tid; idx < 64 * 64; idx += 256) {
        int row = idx >> 6, c4 = idx & 63;
        float4 v = ((const float4*)(xg + (size_t)row * NT))[c4];
        ((float4*)(xs + row * NS))[c4] = v;
    }
    // stage per-segment weights
    const float4* wg = (const float4*)(g_weff + (size_t)bk * 4096);
    for (int idx = tid; idx < 1024; idx += 256)
        ((float4*)wsh)[idx] = wg[idx];
    // stage transposed rw/sw so phase 2 reads broadcast along o
    for (int idx = tid; idx < 4096; idx += 256) {
        int o = idx >> 6, c = idx & 63;
        rwT[c * 64 + o] = rw[idx];
        swT[c * 64 + o] = sw[idx];
    }
    if (tid < 64) {
        bsh[tid]  = g_bias[(size_t)bk * NC + tid];
        rbsh[tid] = rb[tid];
        sbsh[tid] = sb[tid];
    }
    __syncthreads();

    const int ts = tid & 31, to = tid >> 5;
    const int s0 = ts * 8, o0 = to * 8;

    // ---- Phase 1: segment GEMM + bias ----
    float acc[8][8];
    #pragma unroll
    for (int oo = 0; oo < 8; oo++) {
        float bv = bsh[o0 + oo];
        #pragma unroll
        for (int ss = 0; ss < 8; ss++) acc[ss][oo] = bv;
    }

    #pragma unroll 2
    for (int i = 0; i < 64; i++) {
        float4 x0 = *(const float4*)(xs + i * NS + s0);
        float4 x1 = *(const float4*)(xs + i * NS + s0 + 4);
        float4 w0 = *(const float4*)(wsh + i * 64 + o0);
        float4 w1 = *(const float4*)(wsh + i * 64 + o0 + 4);
        float xv[8] = {x0.x, x0.y, x0.z, x0.w, x1.x, x1.y, x1.z, x1.w};
        float wv[8] = {w0.x, w0.y, w0.z, w0.w, w1.x, w1.y, w1.z, w1.w};
        #pragma unroll
        for (int ss = 0; ss < 8; ss++)
            #pragma unroll
            for (int oo = 0; oo < 8; oo++)
                acc[ss][oo] = fmaf(xv[ss], wv[oo], acc[ss][oo]);
    }

    // ---- sin + stage ys[o][s] ----
    #pragma unroll
    for (int oo = 0; oo < 8; oo++) {
        float4 v0, v1;
        v0.x = sinf(acc[0][oo]); v0.y = sinf(acc[1][oo]);
        v0.z = sinf(acc[2][oo]); v0.w = sinf(acc[3][oo]);
        v1.x = sinf(acc[4][oo]); v1.y = sinf(acc[5][oo]);
        v1.z = sinf(acc[6][oo]); v1.w = sinf(acc[7][oo]);
        *(float4*)(ys + (o0 + oo) * NS + s0)     = v0;
        *(float4*)(ys + (o0 + oo) * NS + s0 + 4) = v1;
    }
    __syncthreads();

    // ---- Phase 2: residual + skip channel mixes ----
    float rr[8][8], sk[8][8];
    #pragma unroll
    for (int oo = 0; oo < 8; oo++) {
        float rv = rbsh[o0 + oo], sv = sbsh[o0 + oo];
        #pragma unroll
        for (int ss = 0; ss < 8; ss++) { rr[ss][oo] = rv; sk[ss][oo] = sv; }
    }

    #pragma unroll 2
    for (int c = 0; c < 64; c++) {
        float4 y0 = *(const float4*)(ys + c * NS + s0);
        float4 y1 = *(const float4*)(ys + c * NS + s0 + 4);
        float4 r0 = *(const float4*)(rwT + c * 64 + o0);
        float4 r1 = *(const float4*)(rwT + c * 64 + o0 + 4);
        float4 q0 = *(const float4*)(swT + c * 64 + o0);
        float4 q1 = *(const float4*)(swT + c * 64 + o0 + 4);
        float yv[8] = {y0.x, y0.y, y0.z, y0.w, y1.x, y1.y, y1.z, y1.w};
        float rv[8] = {r0.x, r0.y, r0.z, r0.w, r1.x, r1.y, r1.z, r1.w};
        float qv[8] = {q0.x, q0.y, q0.z, q0.w, q1.x, q1.y, q1.z, q1.w};
        #pragma unroll
        for (int ss = 0; ss < 8; ss++)
            #pragma unroll
            for (int oo = 0; oo < 8; oo++) {
                rr[ss][oo] = fmaf(yv[ss], rv[oo], rr[ss][oo]);
                sk[ss][oo] = fmaf(yv[ss], qv[oo], sk[ss][oo]);
            }
    }

    // ---- Epilogue: (res + x)/2 and skip, written once, coalesced ----
    size_t obase = ((size_t)b * NC) * NT + (size_t)k * NS + s0;
    #pragma unroll
    for (int oo = 0; oo < 8; oo++) {
        int o = o0 + oo;
        float4 xv0 = *(const float4*)(xs + o * NS + s0);
        float4 xv1 = *(const float4*)(xs + o * NS + s0 + 4);
        float4 u0, u1, v0, v1;
        u0.x = 0.5f * (rr[0][oo] + xv0.x); u0.y = 0.5f * (rr[1][oo] + xv0.y);
        u0.z = 0.5f * (rr[2][oo] + xv0.z); u0.w = 0.5f * (rr[3][oo] + xv0.w);
        u1.x = 0.5f * (rr[4][oo] + xv1.x); u1.y = 0.5f * (rr[5][oo] + xv1.y);
        u1.z = 0.5f * (rr[6][oo] + xv1.z); u1.w = 0.5f * (rr[7][oo] + xv1.w);
        v0.x = sk[0][oo]; v0.y = sk[1][oo]; v0.z = sk[2][oo]; v0.w = sk[3][oo];
        v1.x = sk[4][oo]; v1.y = sk[5][oo]; v1.z = sk[6][oo]; v1.w = sk[7][oo];
        *(float4*)(out_res  + obase + (size_t)o * NT)     = u0;
        *(float4*)(out_res  + obase + (size_t)o * NT + 4) = u1;
        *(float4*)(out_skip + obase + (size_t)o * NT)     = v0;
        *(float4*)(out_skip + obase + (size_t)o * NT + 4) = v1;
    }
}

// ---------------------------------------------------------------------------
extern "C" void kernel_launch(void* const* d_in, const int* in_sizes, int n_in,
                              void* d_out, int out_size)
{
    const float* x   = (const float*)d_in[0];
    const float* z   = (const float*)d_in[1];
    const float* wm1 = (const float*)d_in[2];
    const float* wb1 = (const float*)d_in[3];
    const float* wm2 = (const float*)d_in[4];
    const float* wb2 = (const float*)d_in[5];
    const float* bm1 = (const float*)d_in[6];
    const float* bb1 = (const float*)d_in[7];
    const float* bm2 = (const float*)d_in[8];
    const float* bb2 = (const float*)d_in[9];
    const float* rw  = (const float*)d_in[10];
    const float* rb  = (const float*)d_in[11];
    const float* sw  = (const float*)d_in[12];
    const float* sb  = (const float*)d_in[13];

    float* out_res  = (float*)d_out;
    float* out_skip = out_res + (size_t)NB * NC * NT;

    // Kernel 1: fold KSZ taps (131072 elements)
    fold_kernel<<<512, 256>>>(wm2, wb2);

    // Kernel 2: hypernet (128 blocks: 8 k-groups x 16 batches)
    dim3 gB(8, 16);
    hyper_kernel<<<gB, 256>>>(z, wm1, wb1, bm1, bb1, bm2, bb2);

    // Kernel 3: fused main pass (one CTA per (b,k) segment)
    const size_t SMEM = (size_t)(2 * 64 * 256 + 3 * 4096 + 3 * 64) * sizeof(float);
    cudaFuncSetAttribute(main_kernel,
                         cudaFuncAttributeMaxDynamicSharedMemorySize, (int)SMEM);
    main_kernel<<<NB * NK, 256, SMEM>>>(x, rw, rb, sw, sb, out_res, out_skip);
}

// round 13
// speedup vs baseline: 1.2957x; 1.2957x over previous
#include <cuda_runtime.h>
#include <math.h>

#define NB 16
#define NT 32768
#define NK 128
#define NS 256     // samples per segment (T/K)
#define NC 64      // in/out channels
#define NZ 64
#define NH 32

// Scratch (allocation-free: __device__ globals)
__device__ float g_wm2eff[4096 * 32];                 // KSZ-folded hypernet matrix
__device__ float g_wb2eff[4096];
__device__ float g_weff[(size_t)NB * NK * 4096];      // per-(b,k) 64x64 weights, [bk][i*64+o]
__device__ float g_bias[NB * NK * NC];                // per-(b,k) bias

// ---- packed f32x2 helpers (FFMA2 — only reachable via PTX) ----
__device__ __forceinline__ unsigned long long pack2(float lo, float hi) {
    unsigned long long r;
    asm("mov.b64 %0, {%1, %2};" : "=l"(r) : "f"(lo), "f"(hi));
    return r;
}
__device__ __forceinline__ unsigned long long bcast2(float v) {
    unsigned long long r;
    asm("mov.b64 %0, {%1, %1};" : "=l"(r) : "f"(v));
    return r;
}
__device__ __forceinline__ void fma2(unsigned long long& d,
                                     unsigned long long a, unsigned long long b) {
    asm("fma.rn.f32x2 %0, %1, %2, %0;" : "+l"(d) : "l"(a), "l"(b));
}
__device__ __forceinline__ void unpack2(unsigned long long v, float& lo, float& hi) {
    asm("mov.b64 {%0, %1}, %2;" : "=f"(lo), "=f"(hi) : "l"(v));
}

// ---------------------------------------------------------------------------
// Kernel 1: fold the KSZ tap sum into wm2/wb2.
// ---------------------------------------------------------------------------
__global__ void fold_kernel(const float* __restrict__ wm2,
                            const float* __restrict__ wb2)
{
    int idx = blockIdx.x * 256 + threadIdx.x;
    if (idx < 4096 * 32) {
        int r = idx >> 5, h = idx & 31;
        g_wm2eff[idx] = wm2[r * 32 + h] + wm2[(4096 + r) * 32 + h]
                      + wm2[(8192 + r) * 32 + h];
    }
    if (idx < 4096) {
        g_wb2eff[idx] = wb2[idx] + wb2[4096 + idx] + wb2[8192 + idx];
    }
}

// ---------------------------------------------------------------------------
// Kernel 2: hypernet (per-(b,k) 64x64 weights + bias into scratch).
// ---------------------------------------------------------------------------
__global__ void __launch_bounds__(256) hyper_kernel(
    const float* __restrict__ z,
    const float* __restrict__ wm1, const float* __restrict__ wb1,
    const float* __restrict__ bm1, const float* __restrict__ bb1,
    const float* __restrict__ bm2, const float* __restrict__ bb2)
{
    __shared__ float zsh[16 * 64];
    __shared__ float hsh[16 * 32];
    __shared__ float hbsh[16 * 32];

    int tid = threadIdx.x;
    int b   = blockIdx.y;
    int k0  = blockIdx.x * 16;

    for (int idx = tid; idx < 16 * 64; idx += 256) {
        int zc = idx >> 4, kk = idx & 15;
        zsh[kk * 64 + zc] = z[((size_t)b * NZ + zc) * NK + k0 + kk];
    }
    __syncthreads();

    for (int oi = tid; oi < 1024; oi += 256) {
        int kk = oi >> 6;
        int j  = oi & 63;
        const float* m;
        float bv;
        if (j < 32) { m = wm1 + j * 64;        bv = wb1[j]; }
        else        { m = bm1 + (j - 32) * 64; bv = bb1[j - 32]; }
        float a = bv;
        #pragma unroll
        for (int zc = 0; zc < 64; zc++) a = fmaf(m[zc], zsh[kk * 64 + zc], a);
        a = fmaxf(a, 0.0f);
        if (j < 32) hsh[kk * 32 + j] = a;
        else        hbsh[kk * 32 + (j - 32)] = a;
    }
    __syncthreads();

    for (int r = tid; r < 4096; r += 256) {
        float wrow[32];
        const float4* wp = (const float4*)(g_wm2eff + (size_t)r * 32);
        #pragma unroll
        for (int q = 0; q < 8; q++) {
            float4 v = wp[q];
            wrow[q * 4 + 0] = v.x; wrow[q * 4 + 1] = v.y;
            wrow[q * 4 + 2] = v.z; wrow[q * 4 + 3] = v.w;
        }
        float wb = g_wb2eff[r];
        for (int kk = 0; kk < 16; kk++) {
            float a = wb;
            #pragma unroll
            for (int h = 0; h < 32; h++) a = fmaf(wrow[h], hsh[kk * 32 + h], a);
            g_weff[((size_t)(b * NK + k0 + kk)) * 4096 + r] = a;
        }
    }

    for (int oi = tid; oi < 1024; oi += 256) {
        int kk = oi >> 6;
        int o  = oi & 63;
        float a = bb2[o];
        #pragma unroll
        for (int h = 0; h < 32; h++) a = fmaf(bm2[o * 32 + h], hbsh[kk * 32 + h], a);
        g_bias[((size_t)(b * NK + k0 + kk)) * NC + o] = a;
    }
}

// ---------------------------------------------------------------------------
// Kernel 3: fused main pass. One CTA per (b,k) segment, FFMA2 throughout.
// Accumulators are f32x2 pairs along the o-axis; w/rw/sw/bias pairs load
// natively as 64-bit words from smem, the shared operand is broadcast-packed.
// ---------------------------------------------------------------------------
__global__ void __launch_bounds__(256, 1) main_kernel(
    const float* __restrict__ x,
    const float* __restrict__ rw, const float* __restrict__ rb,
    const float* __restrict__ sw, const float* __restrict__ sb,
    float* __restrict__ out_res, float* __restrict__ out_skip)
{
    extern __shared__ float sm[];
    float* xs   = sm;                 // [64][256] x segment
    float* ys   = xs + 64 * 256;      // [64][256] sin(y)
    float* wsh  = ys + 64 * 256;      // [64][64] w_eff (i, o)
    float* rwT  = wsh + 4096;         // [c][o]
    float* swT  = rwT + 4096;         // [c][o]
    float* bsh  = swT + 4096;         // [64]
    float* rbsh = bsh + 64;
    float* sbsh = rbsh + 64;

    int tid = threadIdx.x;
    int bk  = blockIdx.x;
    int b   = bk >> 7, k = bk & 127;

    // stage x segment
    const float* xg = x + ((size_t)b * NC) * NT + (size_t)k * NS;
    for (int idx = tid; idx < 64 * 64; idx += 256) {
        int row = idx >> 6, c4 = idx & 63;
        float4 v = ((const float4*)(xg + (size_t)row * NT))[c4];
        ((float4*)(xs + row * NS))[c4] = v;
    }
    // stage per-segment weights
    const float4* wg = (const float4*)(g_weff + (size_t)bk * 4096);
    for (int idx = tid; idx < 1024; idx += 256)
        ((float4*)wsh)[idx] = wg[idx];
    // stage transposed rw/sw
    for (int idx = tid; idx < 4096; idx += 256) {
        int o = idx >> 6, c = idx & 63;
        rwT[c * 64 + o] = rw[idx];
        swT[c * 64 + o] = sw[idx];
    }
    if (tid < 64) {
        bsh[tid]  = g_bias[(size_t)bk * NC + tid];
        rbsh[tid] = rb[tid];
        sbsh[tid] = sb[tid];
    }
    __syncthreads();

    const int ts = tid & 31, to = tid >> 5;
    const int s0 = ts * 8, o0 = to * 8;

    // ---- Phase 1: segment GEMM + bias (f32x2 pairs along o) ----
    unsigned long long acc[8][4];
    {
        ulonglong2 bA = *(const ulonglong2*)(bsh + o0);
        ulonglong2 bB = *(const ulonglong2*)(bsh + o0 + 4);
        #pragma unroll
        for (int ss = 0; ss < 8; ss++) {
            acc[ss][0] = bA.x; acc[ss][1] = bA.y;
            acc[ss][2] = bB.x; acc[ss][3] = bB.y;
        }
    }

    #pragma unroll 2
    for (int i = 0; i < 64; i++) {
        ulonglong2 wA = *(const ulonglong2*)(wsh + i * 64 + o0);
        ulonglong2 wB = *(const ulonglong2*)(wsh + i * 64 + o0 + 4);
        float4 x0 = *(const float4*)(xs + i * NS + s0);
        float4 x1 = *(const float4*)(xs + i * NS + s0 + 4);
        unsigned long long xp[8];
        xp[0] = bcast2(x0.x); xp[1] = bcast2(x0.y);
        xp[2] = bcast2(x0.z); xp[3] = bcast2(x0.w);
        xp[4] = bcast2(x1.x); xp[5] = bcast2(x1.y);
        xp[6] = bcast2(x1.z); xp[7] = bcast2(x1.w);
        #pragma unroll
        for (int ss = 0; ss < 8; ss++) {
            fma2(acc[ss][0], xp[ss], wA.x);
            fma2(acc[ss][1], xp[ss], wA.y);
            fma2(acc[ss][2], xp[ss], wB.x);
            fma2(acc[ss][3], xp[ss], wB.y);
        }
    }

    // ---- sin + stage ys[o][s] ----
    {
        float yv[8][8];
        #pragma unroll
        for (int ss = 0; ss < 8; ss++)
            #pragma unroll
            for (int p = 0; p < 4; p++)
                unpack2(acc[ss][p], yv[ss][2 * p], yv[ss][2 * p + 1]);
        #pragma unroll
        for (int ss = 0; ss < 8; ss++)
            #pragma unroll
            for (int oo = 0; oo < 8; oo++)
                yv[ss][oo] = __sinf(yv[ss][oo]);
        #pragma unroll
        for (int oo = 0; oo < 8; oo++) {
            float4 v0, v1;
            v0.x = yv[0][oo]; v0.y = yv[1][oo]; v0.z = yv[2][oo]; v0.w = yv[3][oo];
            v1.x = yv[4][oo]; v1.y = yv[5][oo]; v1.z = yv[6][oo]; v1.w = yv[7][oo];
            *(float4*)(ys + (o0 + oo) * NS + s0)     = v0;
            *(float4*)(ys + (o0 + oo) * NS + s0 + 4) = v1;
        }
    }
    __syncthreads();

    // ---- Phase 2: residual + skip channel mixes (f32x2) ----
    unsigned long long rr2[8][4], sk2[8][4];
    {
        ulonglong2 rA = *(const ulonglong2*)(rbsh + o0);
        ulonglong2 rB = *(const ulonglong2*)(rbsh + o0 + 4);
        ulonglong2 sA = *(const ulonglong2*)(sbsh + o0);
        ulonglong2 sB = *(const ulonglong2*)(sbsh + o0 + 4);
        #pragma unroll
        for (int ss = 0; ss < 8; ss++) {
            rr2[ss][0] = rA.x; rr2[ss][1] = rA.y;
            rr2[ss][2] = rB.x; rr2[ss][3] = rB.y;
            sk2[ss][0] = sA.x; sk2[ss][1] = sA.y;
            sk2[ss][2] = sB.x; sk2[ss][3] = sB.y;
        }
    }

    #pragma unroll 2
    for (int c = 0; c < 64; c++) {
        ulonglong2 rwA = *(const ulonglong2*)(rwT + c * 64 + o0);
        ulonglong2 rwB = *(const ulonglong2*)(rwT + c * 64 + o0 + 4);
        ulonglong2 swA = *(const ulonglong2*)(swT + c * 64 + o0);
        ulonglong2 swB = *(const ulonglong2*)(swT + c * 64 + o0 + 4);
        float4 y0 = *(const float4*)(ys + c * NS + s0);
        float4 y1 = *(const float4*)(ys + c * NS + s0 + 4);
        unsigned long long yp[8];
        yp[0] = bcast2(y0.x); yp[1] = bcast2(y0.y);
        yp[2] = bcast2(y0.z); yp[3] = bcast2(y0.w);
        yp[4] = bcast2(y1.x); yp[5] = bcast2(y1.y);
        yp[6] = bcast2(y1.z); yp[7] = bcast2(y1.w);
        #pragma unroll
        for (int ss = 0; ss < 8; ss++) {
            fma2(rr2[ss][0], yp[ss], rwA.x);
            fma2(rr2[ss][1], yp[ss], rwA.y);
            fma2(rr2[ss][2], yp[ss], rwB.x);
            fma2(rr2[ss][3], yp[ss], rwB.y);
            fma2(sk2[ss][0], yp[ss], swA.x);
            fma2(sk2[ss][1], yp[ss], swA.y);
            fma2(sk2[ss][2], yp[ss], swB.x);
            fma2(sk2[ss][3], yp[ss], swB.y);
        }
    }

    // ---- Epilogue: (res + x)/2 and skip ----
    size_t obase = ((size_t)b * NC) * NT + (size_t)k * NS + s0;
    #pragma unroll
    for (int p = 0; p < 4; p++) {
        float ra[8], rbv[8], sa[8], sbv[8];
        #pragma unroll
        for (int ss = 0; ss < 8; ss++) {
            unpack2(rr2[ss][p], ra[ss], rbv[ss]);
            unpack2(sk2[ss][p], sa[ss], sbv[ss]);
        }
        int oA = o0 + 2 * p, oB = oA + 1;

        float4 xa0 = *(const float4*)(xs + oA * NS + s0);
        float4 xa1 = *(const float4*)(xs + oA * NS + s0 + 4);
        float4 xb0 = *(const float4*)(xs + oB * NS + s0);
        float4 xb1 = *(const float4*)(xs + oB * NS + s0 + 4);

        float4 u0, u1, v0, v1;
        u0.x = 0.5f * (ra[0] + xa0.x); u0.y = 0.5f * (ra[1] + xa0.y);
        u0.z = 0.5f * (ra[2] + xa0.z); u0.w = 0.5f * (ra[3] + xa0.w);
        u1.x = 0.5f * (ra[4] + xa1.x); u1.y = 0.5f * (ra[5] + xa1.y);
        u1.z = 0.5f * (ra[6] + xa1.z); u1.w = 0.5f * (ra[7] + xa1.w);
        v0.x = sa[0]; v0.y = sa[1]; v0.z = sa[2]; v0.w = sa[3];
        v1.x = sa[4]; v1.y = sa[5]; v1.z = sa[6]; v1.w = sa[7];
        *(float4*)(out_res  + obase + (size_t)oA * NT)     = u0;
        *(float4*)(out_res  + obase + (size_t)oA * NT + 4) = u1;
        *(float4*)(out_skip + obase + (size_t)oA * NT)     = v0;
        *(float4*)(out_skip + obase + (size_t)oA * NT + 4) = v1;

        u0.x = 0.5f * (rbv[0] + xb0.x); u0.y = 0.5f * (rbv[1] + xb0.y);
        u0.z = 0.5f * (rbv[2] + xb0.z); u0.w = 0.5f * (rbv[3] + xb0.w);
        u1.x = 0.5f * (rbv[4] + xb1.x); u1.y = 0.5f * (rbv[5] + xb1.y);
        u1.z = 0.5f * (rbv[6] + xb1.z); u1.w = 0.5f * (rbv[7] + xb1.w);
        v0.x = sbv[0]; v0.y = sbv[1]; v0.z = sbv[2]; v0.w = sbv[3];
        v1.x = sbv[4]; v1.y = sbv[5]; v1.z = sbv[6]; v1.w = sbv[7];
        *(float4*)(out_res  + obase + (size_t)oB * NT)     = u0;
        *(float4*)(out_res  + obase + (size_t)oB * NT + 4) = u1;
        *(float4*)(out_skip + obase + (size_t)oB * NT)     = v0;
        *(float4*)(out_skip + obase + (size_t)oB * NT + 4) = v1;
    }
}

// ---------------------------------------------------------------------------
extern "C" void kernel_launch(void* const* d_in, const int* in_sizes, int n_in,
                              void* d_out, int out_size)
{
    const float* x   = (const float*)d_in[0];
    const float* z   = (const float*)d_in[1];
    const float* wm1 = (const float*)d_in[2];
    const float* wb1 = (const float*)d_in[3];
    const float* wm2 = (const float*)d_in[4];
    const float* wb2 = (const float*)d_in[5];
    const float* bm1 = (const float*)d_in[6];
    const float* bb1 = (const float*)d_in[7];
    const float* bm2 = (const float*)d_in[8];
    const float* bb2 = (const float*)d_in[9];
    const float* rw  = (const float*)d_in[10];
    const float* rb  = (const float*)d_in[11];
    const float* sw  = (const float*)d_in[12];
    const float* sb  = (const float*)d_in[13];

    float* out_res  = (float*)d_out;
    float* out_skip = out_res + (size_t)NB * NC * NT;

    fold_kernel<<<512, 256>>>(wm2, wb2);

    dim3 gB(8, 16);
    hyper_kernel<<<gB, 256>>>(z, wm1, wb1, bm1, bb1, bm2, bb2);

    const size_t SMEM = (size_t)(2 * 64 * 256 + 3 * 4096 + 3 * 64) * sizeof(float);
    cudaFuncSetAttribute(main_kernel,
                         cudaFuncAttributeMaxDynamicSharedMemorySize, (int)SMEM);
    main_kernel<<<NB * NK, 256, SMEM>>>(x, rw, rb, sw, sb, out_res, out_skip);
}

// round 14
// speedup vs baseline: 1.5456x; 1.1929x over previous
#include <cuda_runtime.h>
#include <math.h>

#define NB 16
#define NT 32768
#define NK 128
#define NS 256     // samples per segment (T/K)
#define NC 64      // in/out channels
#define NZ 64
#define NH 32

// Scratch (allocation-free: __device__ globals)
__device__ float g_wm2eff[4096 * 32];                 // KSZ-folded hypernet matrix
__device__ float g_wb2eff[4096];
__device__ float g_weff[(size_t)NB * NK * 4096];      // per-(b,k) 64x64 weights, [bk][i*64+o]
__device__ float g_bias[NB * NK * NC];                // per-(b,k) bias

// ---- packed f32x2 helpers (FFMA2 — only reachable via PTX) ----
__device__ __forceinline__ unsigned long long bcast2(float v) {
    unsigned long long r;
    asm("mov.b64 %0, {%1, %1};" : "=l"(r) : "f"(v));
    return r;
}
__device__ __forceinline__ void fma2(unsigned long long& d,
                                     unsigned long long a, unsigned long long b) {
    asm("fma.rn.f32x2 %0, %1, %2, %0;" : "+l"(d) : "l"(a), "l"(b));
}
__device__ __forceinline__ void unpack2(unsigned long long v, float& lo, float& hi) {
    asm("mov.b64 {%0, %1}, %2;" : "=f"(lo), "=f"(hi) : "l"(v));
}

// ---------------------------------------------------------------------------
// Kernel 1: fold the KSZ tap sum into wm2/wb2.
// ---------------------------------------------------------------------------
__global__ void fold_kernel(const float* __restrict__ wm2,
                            const float* __restrict__ wb2)
{
    int idx = blockIdx.x * 256 + threadIdx.x;
    if (idx < 4096 * 32) {
        int r = idx >> 5, h = idx & 31;
        g_wm2eff[idx] = wm2[r * 32 + h] + wm2[(4096 + r) * 32 + h]
                      + wm2[(8192 + r) * 32 + h];
    }
    if (idx < 4096) {
        g_wb2eff[idx] = wb2[idx] + wb2[4096 + idx] + wb2[8192 + idx];
    }
}

// ---------------------------------------------------------------------------
// Kernel 2: hypernet (per-(b,k) 64x64 weights + bias into scratch).
// ---------------------------------------------------------------------------
__global__ void __launch_bounds__(256) hyper_kernel(
    const float* __restrict__ z,
    const float* __restrict__ wm1, const float* __restrict__ wb1,
    const float* __restrict__ bm1, const float* __restrict__ bb1,
    const float* __restrict__ bm2, const float* __restrict__ bb2)
{
    __shared__ float zsh[16 * 64];
    __shared__ float hsh[16 * 32];
    __shared__ float hbsh[16 * 32];

    int tid = threadIdx.x;
    int b   = blockIdx.y;
    int k0  = blockIdx.x * 16;

    for (int idx = tid; idx < 16 * 64; idx += 256) {
        int zc = idx >> 4, kk = idx & 15;
        zsh[kk * 64 + zc] = z[((size_t)b * NZ + zc) * NK + k0 + kk];
    }
    __syncthreads();

    for (int oi = tid; oi < 1024; oi += 256) {
        int kk = oi >> 6;
        int j  = oi & 63;
        const float* m;
        float bv;
        if (j < 32) { m = wm1 + j * 64;        bv = wb1[j]; }
        else        { m = bm1 + (j - 32) * 64; bv = bb1[j - 32]; }
        float a = bv;
        #pragma unroll
        for (int zc = 0; zc < 64; zc++) a = fmaf(m[zc], zsh[kk * 64 + zc], a);
        a = fmaxf(a, 0.0f);
        if (j < 32) hsh[kk * 32 + j] = a;
        else        hbsh[kk * 32 + (j - 32)] = a;
    }
    __syncthreads();

    for (int r = tid; r < 4096; r += 256) {
        float wrow[32];
        const float4* wp = (const float4*)(g_wm2eff + (size_t)r * 32);
        #pragma unroll
        for (int q = 0; q < 8; q++) {
            float4 v = wp[q];
            wrow[q * 4 + 0] = v.x; wrow[q * 4 + 1] = v.y;
            wrow[q * 4 + 2] = v.z; wrow[q * 4 + 3] = v.w;
        }
        float wb = g_wb2eff[r];
        for (int kk = 0; kk < 16; kk++) {
            float a = wb;
            #pragma unroll
            for (int h = 0; h < 32; h++) a = fmaf(wrow[h], hsh[kk * 32 + h], a);
            g_weff[((size_t)(b * NK + k0 + kk)) * 4096 + r] = a;
        }
    }

    for (int oi = tid; oi < 1024; oi += 256) {
        int kk = oi >> 6;
        int o  = oi & 63;
        float a = bb2[o];
        #pragma unroll
        for (int h = 0; h < 32; h++) a = fmaf(bm2[o * 32 + h], hbsh[kk * 32 + h], a);
        g_bias[((size_t)(b * NK + k0 + kk)) * NC + o] = a;
    }
}

// ---------------------------------------------------------------------------
// Kernel 3: fused main pass. One CTA (512 threads) per (b,k) segment.
// Warp w: o-group (w>>1)*8, s-half (w&1). Thread: 4 contiguous s x 8 o.
// All per-lane smem accesses are lane-stride-16B LDS.128 (conflict-free);
// all weight accesses are warp-uniform broadcasts.
// ---------------------------------------------------------------------------
__global__ void __launch_bounds__(512, 1) main_kernel(
    const float* __restrict__ x,
    const float* __restrict__ rw, const float* __restrict__ rb,
    const float* __restrict__ sw, const float* __restrict__ sb,
    float* __restrict__ out_res, float* __restrict__ out_skip)
{
    extern __shared__ float sm[];
    float* xs   = sm;                 // [64][256] x segment
    float* ys   = xs + 64 * 256;      // [64][256] sin(y)
    float* wsh  = ys + 64 * 256;      // [64][64] w_eff (i, o)
    float* rwT  = wsh + 4096;         // [c][o]
    float* swT  = rwT + 4096;         // [c][o]
    float* bsh  = swT + 4096;         // [64]
    float* rbsh = bsh + 64;
    float* sbsh = rbsh + 64;

    int tid = threadIdx.x;
    int bk  = blockIdx.x;
    int b   = bk >> 7, k = bk & 127;

    // stage x segment: 64 rows x 256 floats
    const float* xg = x + ((size_t)b * NC) * NT + (size_t)k * NS;
    for (int idx = tid; idx < 64 * 64; idx += 512) {
        int row = idx >> 6, c4 = idx & 63;
        float4 v = ((const float4*)(xg + (size_t)row * NT))[c4];
        ((float4*)(xs + row * NS))[c4] = v;
    }
    // stage per-segment weights
    const float4* wg = (const float4*)(g_weff + (size_t)bk * 4096);
    for (int idx = tid; idx < 1024; idx += 512)
        ((float4*)wsh)[idx] = wg[idx];
    // stage transposed rw/sw
    for (int idx = tid; idx < 4096; idx += 512) {
        int o = idx >> 6, c = idx & 63;
        rwT[c * 64 + o] = rw[idx];
        swT[c * 64 + o] = sw[idx];
    }
    if (tid < 64) {
        bsh[tid]  = g_bias[(size_t)bk * NC + tid];
        rbsh[tid] = rb[tid];
        sbsh[tid] = sb[tid];
    }
    __syncthreads();

    const int w    = tid >> 5;
    const int lane = tid & 31;
    const int o0   = (w >> 1) * 8;
    const int sB   = (w & 1) * 128 + lane * 4;   // 4 contiguous s per thread

    // ---- Phase 1: segment GEMM + bias (f32x2 pairs along o) ----
    unsigned long long acc[4][4];
    {
        ulonglong2 bA = *(const ulonglong2*)(bsh + o0);
        ulonglong2 bB = *(const ulonglong2*)(bsh + o0 + 4);
        #pragma unroll
        for (int ss = 0; ss < 4; ss++) {
            acc[ss][0] = bA.x; acc[ss][1] = bA.y;
            acc[ss][2] = bB.x; acc[ss][3] = bB.y;
        }
    }

    #pragma unroll 4
    for (int i = 0; i < 64; i++) {
        ulonglong2 wA = *(const ulonglong2*)(wsh + i * 64 + o0);      // uniform
        ulonglong2 wB = *(const ulonglong2*)(wsh + i * 64 + o0 + 4);  // uniform
        float4 x0 = *(const float4*)(xs + i * NS + sB);               // conflict-free
        unsigned long long xp[4];
        xp[0] = bcast2(x0.x); xp[1] = bcast2(x0.y);
        xp[2] = bcast2(x0.z); xp[3] = bcast2(x0.w);
        #pragma unroll
        for (int ss = 0; ss < 4; ss++) {
            fma2(acc[ss][0], xp[ss], wA.x);
            fma2(acc[ss][1], xp[ss], wA.y);
            fma2(acc[ss][2], xp[ss], wB.x);
            fma2(acc[ss][3], xp[ss], wB.y);
        }
    }

    // ---- sin + stage ys[o][s] ----
    {
        float yv[4][8];
        #pragma unroll
        for (int ss = 0; ss < 4; ss++)
            #pragma unroll
            for (int p = 0; p < 4; p++)
                unpack2(acc[ss][p], yv[ss][2 * p], yv[ss][2 * p + 1]);
        #pragma unroll
        for (int ss = 0; ss < 4; ss++)
            #pragma unroll
            for (int oo = 0; oo < 8; oo++)
                yv[ss][oo] = __sinf(yv[ss][oo]);
        #pragma unroll
        for (int oo = 0; oo < 8; oo++) {
            float4 v0;
            v0.x = yv[0][oo]; v0.y = yv[1][oo]; v0.z = yv[2][oo]; v0.w = yv[3][oo];
            *(float4*)(ys + (o0 + oo) * NS + sB) = v0;                // conflict-free
        }
    }
    __syncthreads();

    // ---- Phase 2: residual + skip channel mixes (f32x2) ----
    unsigned long long rr2[4][4], sk2[4][4];
    {
        ulonglong2 rA = *(const ulonglong2*)(rbsh + o0);
        ulonglong2 rB = *(const ulonglong2*)(rbsh + o0 + 4);
        ulonglong2 sA = *(const ulonglong2*)(sbsh + o0);
        ulonglong2 sBv = *(const ulonglong2*)(sbsh + o0 + 4);
        #pragma unroll
        for (int ss = 0; ss < 4; ss++) {
            rr2[ss][0] = rA.x; rr2[ss][1] = rA.y;
            rr2[ss][2] = rB.x; rr2[ss][3] = rB.y;
            sk2[ss][0] = sA.x; sk2[ss][1] = sA.y;
            sk2[ss][2] = sBv.x; sk2[ss][3] = sBv.y;
        }
    }

    #pragma unroll 4
    for (int c = 0; c < 64; c++) {
        ulonglong2 rwA = *(const ulonglong2*)(rwT + c * 64 + o0);      // uniform
        ulonglong2 rwB = *(const ulonglong2*)(rwT + c * 64 + o0 + 4);
        ulonglong2 swA = *(const ulonglong2*)(swT + c * 64 + o0);
        ulonglong2 swB = *(const ulonglong2*)(swT + c * 64 + o0 + 4);
        float4 y0 = *(const float4*)(ys + c * NS + sB);                // conflict-free
        unsigned long long yp[4];
        yp[0] = bcast2(y0.x); yp[1] = bcast2(y0.y);
        yp[2] = bcast2(y0.z); yp[3] = bcast2(y0.w);
        #pragma unroll
        for (int ss = 0; ss < 4; ss++) {
            fma2(rr2[ss][0], yp[ss], rwA.x);
            fma2(rr2[ss][1], yp[ss], rwA.y);
            fma2(rr2[ss][2], yp[ss], rwB.x);
            fma2(rr2[ss][3], yp[ss], rwB.y);
            fma2(sk2[ss][0], yp[ss], swA.x);
            fma2(sk2[ss][1], yp[ss], swA.y);
            fma2(sk2[ss][2], yp[ss], swB.x);
            fma2(sk2[ss][3], yp[ss], swB.y);
        }
    }

    // ---- Epilogue: (res + x)/2 and skip ----
    size_t obase = ((size_t)b * NC) * NT + (size_t)k * NS + sB;
    #pragma unroll
    for (int p = 0; p < 4; p++) {
        float ra[4], rbv[4], sa[4], sbv[4];
        #pragma unroll
        for (int ss = 0; ss < 4; ss++) {
            unpack2(rr2[ss][p], ra[ss], rbv[ss]);
            unpack2(sk2[ss][p], sa[ss], sbv[ss]);
        }
        int oA = o0 + 2 * p, oB = oA + 1;

        float4 xa = *(const float4*)(xs + oA * NS + sB);
        float4 xb = *(const float4*)(xs + oB * NS + sB);

        float4 u, v;
        u.x = 0.5f * (ra[0] + xa.x); u.y = 0.5f * (ra[1] + xa.y);
        u.z = 0.5f * (ra[2] + xa.z); u.w = 0.5f * (ra[3] + xa.w);
        v.x = sa[0]; v.y = sa[1]; v.z = sa[2]; v.w = sa[3];
        *(float4*)(out_res  + obase + (size_t)oA * NT) = u;
        *(float4*)(out_skip + obase + (size_t)oA * NT) = v;

        u.x = 0.5f * (rbv[0] + xb.x); u.y = 0.5f * (rbv[1] + xb.y);
        u.z = 0.5f * (rbv[2] + xb.z); u.w = 0.5f * (rbv[3] + xb.w);
        v.x = sbv[0]; v.y = sbv[1]; v.z = sbv[2]; v.w = sbv[3];
        *(float4*)(out_res  + obase + (size_t)oB * NT) = u;
        *(float4*)(out_skip + obase + (size_t)oB * NT) = v;
    }
}

// ---------------------------------------------------------------------------
extern "C" void kernel_launch(void* const* d_in, const int* in_sizes, int n_in,
                              void* d_out, int out_size)
{
    const float* x   = (const float*)d_in[0];
    const float* z   = (const float*)d_in[1];
    const float* wm1 = (const float*)d_in[2];
    const float* wb1 = (const float*)d_in[3];
    const float* wm2 = (const float*)d_in[4];
    const float* wb2 = (const float*)d_in[5];
    const float* bm1 = (const float*)d_in[6];
    const float* bb1 = (const float*)d_in[7];
    const float* bm2 = (const float*)d_in[8];
    const float* bb2 = (const float*)d_in[9];
    const float* rw  = (const float*)d_in[10];
    const float* rb  = (const float*)d_in[11];
    const float* sw  = (const float*)d_in[12];
    const float* sb  = (const float*)d_in[13];

    float* out_res  = (float*)d_out;
    float* out_skip = out_res + (size_t)NB * NC * NT;

    fold_kernel<<<512, 256>>>(wm2, wb2);

    dim3 gB(8, 16);
    hyper_kernel<<<gB, 256>>>(z, wm1, wb1, bm1, bb1, bm2, bb2);

    const size_t SMEM = (size_t)(2 * 64 * 256 + 3 * 4096 + 3 * 64) * sizeof(float);
    cudaFuncSetAttribute(main_kernel,
                         cudaFuncAttributeMaxDynamicSharedMemorySize, (int)SMEM);
    main_kernel<<<NB * NK, 512, SMEM>>>(x, rw, rb, sw, sb, out_res, out_skip);
}

// round 15
// speedup vs baseline: 1.5461x; 1.0003x over previous
#include <cuda_runtime.h>
#include <math.h>

#define NB 16
#define NT 32768
#define NK 128
#define NS 256     // samples per segment (T/K)
#define NC 64      // in/out channels
#define NZ 64
#define NH 32

// Scratch (allocation-free: __device__ globals)
__device__ float g_wm2eff[4096 * 32];                 // KSZ-folded hypernet matrix
__device__ float g_wb2eff[4096];
__device__ float g_weff[(size_t)NB * NK * 4096];      // per-(b,k) 64x64 weights, [bk][i*64+o]
__device__ float g_bias[NB * NK * NC];                // per-(b,k) bias

// ---- packed f32x2 helpers (FFMA2 — only reachable via PTX) ----
__device__ __forceinline__ unsigned long long bcast2(float v) {
    unsigned long long r;
    asm("mov.b64 %0, {%1, %1};" : "=l"(r) : "f"(v));
    return r;
}
__device__ __forceinline__ void fma2(unsigned long long& d,
                                     unsigned long long a, unsigned long long b) {
    asm("fma.rn.f32x2 %0, %1, %2, %0;" : "+l"(d) : "l"(a), "l"(b));
}
__device__ __forceinline__ void unpack2(unsigned long long v, float& lo, float& hi) {
    asm("mov.b64 {%0, %1}, %2;" : "=f"(lo), "=f"(hi) : "l"(v));
}

// ---------------------------------------------------------------------------
// Kernel 1: fold the KSZ tap sum into wm2/wb2.
// ---------------------------------------------------------------------------
__global__ void fold_kernel(const float* __restrict__ wm2,
                            const float* __restrict__ wb2)
{
    int idx = blockIdx.x * 256 + threadIdx.x;
    if (idx < 4096 * 32) {
        int r = idx >> 5, h = idx & 31;
        g_wm2eff[idx] = wm2[r * 32 + h] + wm2[(4096 + r) * 32 + h]
                      + wm2[(8192 + r) * 32 + h];
    }
    if (idx < 4096) {
        g_wb2eff[idx] = wb2[idx] + wb2[4096 + idx] + wb2[8192 + idx];
    }
}

// ---------------------------------------------------------------------------
// Kernel 2: hypernet (per-(b,k) 64x64 weights + bias into scratch).
// ---------------------------------------------------------------------------
__global__ void __launch_bounds__(256) hyper_kernel(
    const float* __restrict__ z,
    const float* __restrict__ wm1, const float* __restrict__ wb1,
    const float* __restrict__ bm1, const float* __restrict__ bb1,
    const float* __restrict__ bm2, const float* __restrict__ bb2)
{
    __shared__ float zsh[16 * 64];
    __shared__ float hsh[16 * 32];
    __shared__ float hbsh[16 * 32];

    int tid = threadIdx.x;
    int b   = blockIdx.y;
    int k0  = blockIdx.x * 16;

    for (int idx = tid; idx < 16 * 64; idx += 256) {
        int zc = idx >> 4, kk = idx & 15;
        zsh[kk * 64 + zc] = z[((size_t)b * NZ + zc) * NK + k0 + kk];
    }
    __syncthreads();

    for (int oi = tid; oi < 1024; oi += 256) {
        int kk = oi >> 6;
        int j  = oi & 63;
        const float* m;
        float bv;
        if (j < 32) { m = wm1 + j * 64;        bv = wb1[j]; }
        else        { m = bm1 + (j - 32) * 64; bv = bb1[j - 32]; }
        float a = bv;
        #pragma unroll
        for (int zc = 0; zc < 64; zc++) a = fmaf(m[zc], zsh[kk * 64 + zc], a);
        a = fmaxf(a, 0.0f);
        if (j < 32) hsh[kk * 32 + j] = a;
        else        hbsh[kk * 32 + (j - 32)] = a;
    }
    __syncthreads();

    for (int r = tid; r < 4096; r += 256) {
        float wrow[32];
        const float4* wp = (const float4*)(g_wm2eff + (size_t)r * 32);
        #pragma unroll
        for (int q = 0; q < 8; q++) {
            float4 v = wp[q];
            wrow[q * 4 + 0] = v.x; wrow[q * 4 + 1] = v.y;
            wrow[q * 4 + 2] = v.z; wrow[q * 4 + 3] = v.w;
        }
        float wb = g_wb2eff[r];
        for (int kk = 0; kk < 16; kk++) {
            float a = wb;
            #pragma unroll
            for (int h = 0; h < 32; h++) a = fmaf(wrow[h], hsh[kk * 32 + h], a);
            g_weff[((size_t)(b * NK + k0 + kk)) * 4096 + r] = a;
        }
    }

    for (int oi = tid; oi < 1024; oi += 256) {
        int kk = oi >> 6;
        int o  = oi & 63;
        float a = bb2[o];
        #pragma unroll
        for (int h = 0; h < 32; h++) a = fmaf(bm2[o * 32 + h], hbsh[kk * 32 + h], a);
        g_bias[((size_t)(b * NK + k0 + kk)) * NC + o] = a;
    }
}

// ---------------------------------------------------------------------------
// Kernel 3: fused main pass. One CTA (512 threads) per (b,k) segment.
// Warp w: o-group (w>>1)*8, s-half (w&1). Thread: 4 contiguous s x 8 o.
// All per-lane smem accesses are lane-stride-16B LDS.128 (conflict-free);
// all weight accesses are warp-uniform broadcasts.
// ---------------------------------------------------------------------------
__global__ void __launch_bounds__(512, 1) main_kernel(
    const float* __restrict__ x,
    const float* __restrict__ rw, const float* __restrict__ rb,
    const float* __restrict__ sw, const float* __restrict__ sb,
    float* __restrict__ out_res, float* __restrict__ out_skip)
{
    extern __shared__ float sm[];
    float* xs   = sm;                 // [64][256] x segment
    float* ys   = xs + 64 * 256;      // [64][256] sin(y)
    float* wsh  = ys + 64 * 256;      // [64][64] w_eff (i, o)
    float* rwT  = wsh + 4096;         // [c][o]
    float* swT  = rwT + 4096;         // [c][o]
    float* bsh  = swT + 4096;         // [64]
    float* rbsh = bsh + 64;
    float* sbsh = rbsh + 64;

    int tid = threadIdx.x;
    int bk  = blockIdx.x;
    int b   = bk >> 7, k = bk & 127;

    // stage x segment: 64 rows x 256 floats
    const float* xg = x + ((size_t)b * NC) * NT + (size_t)k * NS;
    for (int idx = tid; idx < 64 * 64; idx += 512) {
        int row = idx >> 6, c4 = idx & 63;
        float4 v = ((const float4*)(xg + (size_t)row * NT))[c4];
        ((float4*)(xs + row * NS))[c4] = v;
    }
    // stage per-segment weights
    const float4* wg = (const float4*)(g_weff + (size_t)bk * 4096);
    for (int idx = tid; idx < 1024; idx += 512)
        ((float4*)wsh)[idx] = wg[idx];
    // stage transposed rw/sw
    for (int idx = tid; idx < 4096; idx += 512) {
        int o = idx >> 6, c = idx & 63;
        rwT[c * 64 + o] = rw[idx];
        swT[c * 64 + o] = sw[idx];
    }
    if (tid < 64) {
        bsh[tid]  = g_bias[(size_t)bk * NC + tid];
        rbsh[tid] = rb[tid];
        sbsh[tid] = sb[tid];
    }
    __syncthreads();

    const int w    = tid >> 5;
    const int lane = tid & 31;
    const int o0   = (w >> 1) * 8;
    const int sB   = (w & 1) * 128 + lane * 4;   // 4 contiguous s per thread

    // ---- Phase 1: segment GEMM + bias (f32x2 pairs along o) ----
    unsigned long long acc[4][4];
    {
        ulonglong2 bA = *(const ulonglong2*)(bsh + o0);
        ulonglong2 bB = *(const ulonglong2*)(bsh + o0 + 4);
        #pragma unroll
        for (int ss = 0; ss < 4; ss++) {
            acc[ss][0] = bA.x; acc[ss][1] = bA.y;
            acc[ss][2] = bB.x; acc[ss][3] = bB.y;
        }
    }

    #pragma unroll 4
    for (int i = 0; i < 64; i++) {
        ulonglong2 wA = *(const ulonglong2*)(wsh + i * 64 + o0);      // uniform
        ulonglong2 wB = *(const ulonglong2*)(wsh + i * 64 + o0 + 4);  // uniform
        float4 x0 = *(const float4*)(xs + i * NS + sB);               // conflict-free
        unsigned long long xp[4];
        xp[0] = bcast2(x0.x); xp[1] = bcast2(x0.y);
        xp[2] = bcast2(x0.z); xp[3] = bcast2(x0.w);
        #pragma unroll
        for (int ss = 0; ss < 4; ss++) {
            fma2(acc[ss][0], xp[ss], wA.x);
            fma2(acc[ss][1], xp[ss], wA.y);
            fma2(acc[ss][2], xp[ss], wB.x);
            fma2(acc[ss][3], xp[ss], wB.y);
        }
    }

    // ---- sin + stage ys[o][s] ----
    {
        float yv[4][8];
        #pragma unroll
        for (int ss = 0; ss < 4; ss++)
            #pragma unroll
            for (int p = 0; p < 4; p++)
                unpack2(acc[ss][p], yv[ss][2 * p], yv[ss][2 * p + 1]);
        #pragma unroll
        for (int ss = 0; ss < 4; ss++)
            #pragma unroll
            for (int oo = 0; oo < 8; oo++)
                yv[ss][oo] = __sinf(yv[ss][oo]);
        #pragma unroll
        for (int oo = 0; oo < 8; oo++) {
            float4 v0;
            v0.x = yv[0][oo]; v0.y = yv[1][oo]; v0.z = yv[2][oo]; v0.w = yv[3][oo];
            *(float4*)(ys + (o0 + oo) * NS + sB) = v0;                // conflict-free
        }
    }
    __syncthreads();

    // ---- Phase 2: residual + skip channel mixes (f32x2) ----
    unsigned long long rr2[4][4], sk2[4][4];
    {
        ulonglong2 rA = *(const ulonglong2*)(rbsh + o0);
        ulonglong2 rB = *(const ulonglong2*)(rbsh + o0 + 4);
        ulonglong2 sA = *(const ulonglong2*)(sbsh + o0);
        ulonglong2 sBv = *(const ulonglong2*)(sbsh + o0 + 4);
        #pragma unroll
        for (int ss = 0; ss < 4; ss++) {
            rr2[ss][0] = rA.x; rr2[ss][1] = rA.y;
            rr2[ss][2] = rB.x; rr2[ss][3] = rB.y;
            sk2[ss][0] = sA.x; sk2[ss][1] = sA.y;
            sk2[ss][2] = sBv.x; sk2[ss][3] = sBv.y;
        }
    }

    #pragma unroll 4
    for (int c = 0; c < 64; c++) {
        ulonglong2 rwA = *(const ulonglong2*)(rwT + c * 64 + o0);      // uniform
        ulonglong2 rwB = *(const ulonglong2*)(rwT + c * 64 + o0 + 4);
        ulonglong2 swA = *(const ulonglong2*)(swT + c * 64 + o0);
        ulonglong2 swB = *(const ulonglong2*)(swT + c * 64 + o0 + 4);
        float4 y0 = *(const float4*)(ys + c * NS + sB);                // conflict-free
        unsigned long long yp[4];
        yp[0] = bcast2(y0.x); yp[1] = bcast2(y0.y);
        yp[2] = bcast2(y0.z); yp[3] = bcast2(y0.w);
        #pragma unroll
        for (int ss = 0; ss < 4; ss++) {
            fma2(rr2[ss][0], yp[ss], rwA.x);
            fma2(rr2[ss][1], yp[ss], rwA.y);
            fma2(rr2[ss][2], yp[ss], rwB.x);
            fma2(rr2[ss][3], yp[ss], rwB.y);
            fma2(sk2[ss][0], yp[ss], swA.x);
            fma2(sk2[ss][1], yp[ss], swA.y);
            fma2(sk2[ss][2], yp[ss], swB.x);
            fma2(sk2[ss][3], yp[ss], swB.y);
        }
    }

    // ---- Epilogue: (res + x)/2 and skip ----
    size_t obase = ((size_t)b * NC) * NT + (size_t)k * NS + sB;
    #pragma unroll
    for (int p = 0; p < 4; p++) {
        float ra[4], rbv[4], sa[4], sbv[4];
        #pragma unroll
        for (int ss = 0; ss < 4; ss++) {
            unpack2(rr2[ss][p], ra[ss], rbv[ss]);
            unpack2(sk2[ss][p], sa[ss], sbv[ss]);
        }
        int oA = o0 + 2 * p, oB = oA + 1;

        float4 xa = *(const float4*)(xs + oA * NS + sB);
        float4 xb = *(const float4*)(xs + oB * NS + sB);

        float4 u, v;
        u.x = 0.5f * (ra[0] + xa.x); u.y = 0.5f * (ra[1] + xa.y);
        u.z = 0.5f * (ra[2] + xa.z); u.w = 0.5f * (ra[3] + xa.w);
        v.x = sa[0]; v.y = sa[1]; v.z = sa[2]; v.w = sa[3];
        *(float4*)(out_res  + obase + (size_t)oA * NT) = u;
        *(float4*)(out_skip + obase + (size_t)oA * NT) = v;

        u.x = 0.5f * (rbv[0] + xb.x); u.y = 0.5f * (rbv[1] + xb.y);
        u.z = 0.5f * (rbv[2] + xb.z); u.w = 0.5f * (rbv[3] + xb.w);
        v.x = sbv[0]; v.y = sbv[1]; v.z = sbv[2]; v.w = sbv[3];
        *(float4*)(out_res  + obase + (size_t)oB * NT) = u;
        *(float4*)(out_skip + obase + (size_t)oB * NT) = v;
    }
}

// ---------------------------------------------------------------------------
extern "C" void kernel_launch(void* const* d_in, const int* in_sizes, int n_in,
                              void* d_out, int out_size)
{
    const float* x   = (const float*)d_in[0];
    const float* z   = (const float*)d_in[1];
    const float* wm1 = (const float*)d_in[2];
    const float* wb1 = (const float*)d_in[3];
    const float* wm2 = (const float*)d_in[4];
    const float* wb2 = (const float*)d_in[5];
    const float* bm1 = (const float*)d_in[6];
    const float* bb1 = (const float*)d_in[7];
    const float* bm2 = (const float*)d_in[8];
    const float* bb2 = (const float*)d_in[9];
    const float* rw  = (const float*)d_in[10];
    const float* rb  = (const float*)d_in[11];
    const float* sw  = (const float*)d_in[12];
    const float* sb  = (const float*)d_in[13];

    float* out_res  = (float*)d_out;
    float* out_skip = out_res + (size_t)NB * NC * NT;

    fold_kernel<<<512, 256>>>(wm2, wb2);

    dim3 gB(8, 16);
    hyper_kernel<<<gB, 256>>>(z, wm1, wb1, bm1, bb1, bm2, bb2);

    const size_t SMEM = (size_t)(2 * 64 * 256 + 3 * 4096 + 3 * 64) * sizeof(float);
    cudaFuncSetAttribute(main_kernel,
                         cudaFuncAttributeMaxDynamicSharedMemorySize, (int)SMEM);
    main_kernel<<<NB * NK, 512, SMEM>>>(x, rw, rb, sw, sb, out_res, out_skip);
}